// round 6
// baseline (speedup 1.0000x reference)
#include <cuda_runtime.h>
#include <cuda_fp16.h>
#include <cstdint>

#define BB 16
#define LQ 256
#define LK 4096

typedef unsigned long long ull;

// ---------------- device scratch (no allocation allowed) --------------------
__device__ __align__(16) __half g_qh [BB * LQ * 64];         // Q proj, f16, pre-scaled
__device__ __align__(16) __half g_kh [(long)BB * LK * 64];   // K proj, f16
__device__ __align__(16) __half g_wth[(long)BB * 64 * LK];   // Wt[b][d][kk] = [m*v | m]

// ---------------- helpers ----------------------------------------------------
__device__ __forceinline__ uint32_t smem_u32(const void* p) {
    uint32_t a;
    asm("{ .reg .u64 t; cvta.to.shared.u64 t, %1; cvt.u32.u64 %0, t; }" : "=r"(a) : "l"(p));
    return a;
}
__device__ __forceinline__ uint32_t f16x2_of(float lo, float hi) {
    uint32_t r; asm("cvt.rn.f16x2.f32 %0, %1, %2;" : "=r"(r) : "f"(hi), "f"(lo)); return r;
}
__device__ __forceinline__ uint32_t ex2x2(uint32_t a) {
    uint32_t r; asm("ex2.approx.f16x2 %0, %1;" : "=r"(r) : "r"(a)); return r;
}
__device__ __forceinline__ ull pack2(float lo, float hi) {
    ull r; asm("mov.b64 %0, {%1,%2};" : "=l"(r) : "f"(lo), "f"(hi)); return r;
}
__device__ __forceinline__ void unpack2(ull v, float& lo, float& hi) {
    asm("mov.b64 {%0,%1}, %2;" : "=f"(lo), "=f"(hi) : "l"(v));
}
__device__ __forceinline__ ull ffma2(ull a, ull b, ull c) {
    ull d; asm("fma.rn.f32x2 %0, %1, %2, %3;" : "=l"(d) : "l"(a), "l"(b), "l"(c));
    return d;
}
__device__ __forceinline__ void cp16(uint32_t dst, const void* src) {
    asm volatile("cp.async.ca.shared.global [%0], [%1], 16;" :: "r"(dst), "l"(src));
}
#define CP_COMMIT() asm volatile("cp.async.commit_group;" ::: "memory")
#define CP_WAIT(n)  asm volatile("cp.async.wait_group %0;" :: "n"(n) : "memory")

__device__ __forceinline__ void ldsm_x2(uint32_t& r0, uint32_t& r1, uint32_t a) {
    asm volatile("ldmatrix.sync.aligned.m8n8.x2.shared.b16 {%0,%1}, [%2];"
                 : "=r"(r0), "=r"(r1) : "r"(a));
}
__device__ __forceinline__ void ldsm_x4(uint32_t* r, uint32_t a) {
    asm volatile("ldmatrix.sync.aligned.m8n8.x4.shared.b16 {%0,%1,%2,%3}, [%4];"
                 : "=r"(r[0]), "=r"(r[1]), "=r"(r[2]), "=r"(r[3]) : "r"(a));
}
__device__ __forceinline__ void mma_acc(float* d, const uint32_t* a, const uint32_t* b) {
    asm volatile("mma.sync.aligned.m16n8k16.row.col.f32.f16.f16.f32 "
        "{%0,%1,%2,%3}, {%4,%5,%6,%7}, {%8,%9}, {%0,%1,%2,%3};"
        : "+f"(d[0]), "+f"(d[1]), "+f"(d[2]), "+f"(d[3])
        : "r"(a[0]), "r"(a[1]), "r"(a[2]), "r"(a[3]), "r"(b[0]), "r"(b[1]));
}
__device__ __forceinline__ void mma_zro(float* d, const uint32_t* a, const uint32_t* b) {
    asm volatile("mma.sync.aligned.m16n8k16.row.col.f32.f16.f16.f32 "
        "{%0,%1,%2,%3}, {%4,%5,%6,%7}, {%8,%9}, {%10,%10,%10,%10};"
        : "=f"(d[0]), "=f"(d[1]), "=f"(d[2]), "=f"(d[3])
        : "r"(a[0]), "r"(a[1]), "r"(a[2]), "r"(a[3]), "r"(b[0]), "r"(b[1]), "f"(0.0f));
}

#define QSCALE 0.36067376022224085f   // 0.25 * log2(e)

// ---------------- fused prep: proj-q | proj-k | Wt build --------------------
// grid 1600: [0,64) proj q, [64,1088) proj k, [1088,1600) wt
__global__ void __launch_bounds__(256) prep_kernel(
    const float* __restrict__ qin, const float* __restrict__ kin,
    const float* __restrict__ v, const int* __restrict__ m,
    const float* __restrict__ Wq, const float* __restrict__ bq,
    const float* __restrict__ Wk, const float* __restrict__ bk)
{
    __shared__ __align__(16) float Wsh[64 * 64];
    __shared__ __align__(16) float Ish[64 * 68];
    const int bid = blockIdx.x, t = threadIdx.x;

    if (bid < 1088) {
        const int isq = (bid < 64);
        const float* in   = isq ? qin : kin;
        const float* W    = isq ? Wq : Wk;
        const float* bias = isq ? bq : bk;
        const float scale = isq ? QSCALE : 1.0f;
        __half* outp = isq ? g_qh : g_kh;
        const long row0 = (long)(isq ? bid : bid - 64) * 64;
        const float4* ing = (const float4*)(in + row0 * 64);
        #pragma unroll
        for (int i = t; i < 1024; i += 256) ((float4*)Wsh)[i] = ((const float4*)W)[i];
        #pragma unroll
        for (int i = t; i < 1024; i += 256) {
            int rr = i >> 4, c = i & 15;
            *(float4*)&Ish[rr * 68 + c * 4] = ing[i];
        }
        __syncthreads();

        const int e0 = (t & 15) * 4;
        const int rb = (t >> 4) * 4;
        float4 bv = *(const float4*)&bias[e0];
        ull a01 = pack2(bv.x, bv.y), a23 = pack2(bv.z, bv.w);
        ull acc[4][2];
        #pragma unroll
        for (int r = 0; r < 4; r++) { acc[r][0] = a01; acc[r][1] = a23; }
        #pragma unroll 8
        for (int j = 0; j < 64; j++) {
            ulonglong2 w = *(const ulonglong2*)&Wsh[j * 64 + e0];
            #pragma unroll
            for (int r = 0; r < 4; r++) {
                float iv = Ish[(rb + r) * 68 + j];
                ull dv = pack2(iv, iv);
                acc[r][0] = ffma2(dv, w.x, acc[r][0]);
                acc[r][1] = ffma2(dv, w.y, acc[r][1]);
            }
        }
        #pragma unroll
        for (int r = 0; r < 4; r++) {
            float v0, v1, v2, v3;
            unpack2(acc[r][0], v0, v1);
            unpack2(acc[r][1], v2, v3);
            uint2 u;
            u.x = f16x2_of(v0 * scale, v1 * scale);
            u.y = f16x2_of(v2 * scale, v3 * scale);
            *(uint2*)&outp[(row0 + rb + r) * 64 + e0] = u;
        }
    } else {
        // Wt build: g_wth[b][d][kk] = [m*v | m] (f16), via SMEM transpose
        __half* Wsm = (__half*)Wsh;           // [64][144] = 18KB, fits region
        const int id = bid - 1088;
        const int b = id >> 5, kt = id & 31;
        const long base = ((long)b * LK + kt * 128) * 32;
        for (int i = t; i < 4096; i += 256) {
            int kk = i >> 5, d = i & 31;
            float mv = (float)m[base + i];
            float vv = v[base + i];
            Wsm[d * 144 + kk]        = __float2half(mv * vv);
            Wsm[(d + 32) * 144 + kk] = __float2half(mv);
        }
        __syncthreads();
        for (int i = t; i < 1024; i += 256) {
            int row = i >> 4, c = i & 15;
            *(uint4*)(g_wth + ((long)b * 64 + row) * LK + kt * 128 + c * 8) =
                *(uint4*)&Wsm[row * 144 + c * 8];
        }
    }
}

// ---------------- main fused attention: 4-stage pipeline, 1 sync/chunk ------
// grid (8 qt, 16 b), 256 threads = 8 warps: warp = (head h = w&3, kk-half s).
// SMEM (dyn, 1KB-aligned): Q 4KB @0; stages c&3: K 8KB @4096+16384*(c&3), W @+8192.
// Epilogue stage (32KB) / X reuse @4096 (bufs 0,1 — dead by then).
__global__ void __launch_bounds__(256) attn_kernel(
    const float* __restrict__ Wo, const float* __restrict__ bo,
    float* __restrict__ out)
{
    extern __shared__ __align__(16) char smraw[];
    const uint32_t base = smem_u32(smraw);
    const uint32_t sb = (base + 1023) & ~1023u;
    char* shb = smraw + (sb - base);

    const int t = threadIdx.x, l = t & 31, w = t >> 5;
    const int h = w & 3, s = w >> 2;
    const int qt = blockIdx.x, b = blockIdx.y;

    const char*   qg = (const char*)(g_qh + ((long)(b * LQ + qt * 32)) * 64);
    const __half* kg = g_kh  + (long)b * LK * 64;
    const __half* wg = g_wth + (long)b * 64 * LK;

    auto issue = [&](int c) {
        const uint32_t KB = sb + 4096 + (uint32_t)(c & 3) * 16384, WB = KB + 8192;
        const char* ks = (const char*)(kg + (long)c * 64 * 64);
        const int kk0 = c * 64;
        #pragma unroll
        for (int i = t; i < 512; i += 256) {
            uint32_t off = i * 16, sw = off ^ ((off >> 3) & 0x70);
            cp16(KB + sw, ks + off);
            cp16(WB + sw, (const char*)(wg + (long)(i >> 3) * LK + kk0) + (i & 7) * 16);
        }
    };

    // group 0: Q + chunk 0; groups 1,2: chunks 1,2
    {
        uint32_t off = t * 16, sw = off ^ ((off >> 3) & 0x70);
        cp16(sb + sw, qg + off);
    }
    issue(0); CP_COMMIT();
    issue(1); CP_COMMIT();
    issue(2); CP_COMMIT();

    // per-lane ldmatrix address pieces
    const int li = l & 7, sel = (l >> 3) & 1;
    const uint32_t rowb = (uint32_t)li * 128;
    const uint32_t kLane = rowb + (((uint32_t)(h * 32 + sel * 16)) ^ ((uint32_t)li << 4));
    uint32_t wLane[2];
    #pragma unroll
    for (int j = 0; j < 2; j++)
        wLane[j] = rowb + (((uint32_t)(s * 64 + j * 32 + sel * 16)) ^ ((uint32_t)li << 4));

    CP_WAIT(2);
    __syncthreads();

    // Q A-frags (constant over chunks)
    uint32_t aq[2][4];
    {
        const int quad = l >> 3;
        const uint32_t arow = (uint32_t)((quad & 1) * 8 + li) * 128;
        const uint32_t acol = ((uint32_t)(h * 32 + (quad >> 1) * 16)) ^ ((uint32_t)li << 4);
        ldsm_x4(aq[0], sb + 0    + arow + acol);
        ldsm_x4(aq[1], sb + 2048 + arow + acol);
    }

    float O[2][8][4];
    #pragma unroll
    for (int mt = 0; mt < 2; mt++)
        #pragma unroll
        for (int nt = 0; nt < 8; nt++)
            #pragma unroll
            for (int i = 0; i < 4; i++) O[mt][nt][i] = 0.0f;

    for (int c = 0; c < 64; c++) {
        if (c) { CP_WAIT(2); __syncthreads(); }   // chunk c arrived; stage (c-1)&3 free
        if (c + 3 < 64) issue(c + 3);
        CP_COMMIT();                               // empty groups keep wait-count uniform

        const uint32_t KBp = sb + 4096 + (uint32_t)(c & 3) * 16384, WBp = KBp + 8192;

        // GEMM1 + exp: warp covers kk [s*32, s*32+32)
        uint32_t E[2][2][4];
        #pragma unroll
        for (int j = 0; j < 2; j++) {
            uint32_t b0[2], b1[2];
            const uint32_t ka = KBp + (uint32_t)s * 4096 + (uint32_t)(2 * j) * 1024 + kLane;
            ldsm_x2(b0[0], b0[1], ka);
            ldsm_x2(b1[0], b1[1], ka + 1024);
            #pragma unroll
            for (int mt = 0; mt < 2; mt++) {
                float s0[4], s1[4];
                mma_zro(s0, aq[mt], b0);
                mma_zro(s1, aq[mt], b1);
                E[mt][j][0] = ex2x2(f16x2_of(s0[0], s0[1]));
                E[mt][j][1] = ex2x2(f16x2_of(s0[2], s0[3]));
                E[mt][j][2] = ex2x2(f16x2_of(s1[0], s1[1]));
                E[mt][j][3] = ex2x2(f16x2_of(s1[2], s1[3]));
            }
        }

        // GEMM2: O += E . Wt^T over this warp's 32 kk
        #pragma unroll
        for (int j = 0; j < 2; j++) {
            #pragma unroll
            for (int nt = 0; nt < 8; nt++) {
                uint32_t bw[2];
                ldsm_x2(bw[0], bw[1], WBp + (uint32_t)nt * 1024 + wLane[j]);
                mma_acc(O[0][nt], E[0][j], bw);
                mma_acc(O[1][nt], E[1][j], bw);
            }
        }
    }

    // ---- epilogue: reduce kk-halves, X = num/den, out = X @ Wo + bo ---------
    float* stage = (float*)(shb + 4096);   // 4 heads x 32q x 64col (xor-swizzled)
    if (s == 1) {
        #pragma unroll
        for (int mt = 0; mt < 2; mt++)
            #pragma unroll
            for (int nt = 0; nt < 8; nt++)
                #pragma unroll
                for (int i = 0; i < 4; i++) {
                    int q = mt * 16 + (l >> 2) + ((i >> 1) & 1) * 8;
                    int col = nt * 8 + 2 * (l & 3) + (i & 1);
                    stage[h * 2048 + q * 64 + (col ^ ((q & 3) << 3))] = O[mt][nt][i];
                }
    }
    __syncthreads();
    if (s == 0) {
        #pragma unroll
        for (int mt = 0; mt < 2; mt++)
            #pragma unroll
            for (int nt = 0; nt < 8; nt++)
                #pragma unroll
                for (int i = 0; i < 4; i++) {
                    int q = mt * 16 + (l >> 2) + ((i >> 1) & 1) * 8;
                    int col = nt * 8 + 2 * (l & 3) + (i & 1);
                    O[mt][nt][i] += stage[h * 2048 + q * 64 + (col ^ ((q & 3) << 3))];
                }
        #pragma unroll
        for (int mt = 0; mt < 2; mt++)
            #pragma unroll
            for (int nt = 0; nt < 4; nt++)
                #pragma unroll
                for (int i = 0; i < 4; i++)
                    O[mt][nt][i] = __fdividef(O[mt][nt][i], O[mt][nt + 4][i]);
    }
    __syncthreads();
    float* X = (float*)(shb + 4096);       // [32][132]
    if (s == 0) {
        #pragma unroll
        for (int mt = 0; mt < 2; mt++)
            #pragma unroll
            for (int nt = 0; nt < 4; nt++)
                #pragma unroll
                for (int i = 0; i < 4; i++) {
                    int q = mt * 16 + (l >> 2) + ((i >> 1) & 1) * 8;
                    int col = h * 32 + nt * 8 + 2 * (l & 3) + (i & 1);
                    X[q * 132 + col] = O[mt][nt][i];
                }
    }
    __syncthreads();

    const int q = t >> 3, lat0 = (t & 7) * 4;
    float acc[4];
    #pragma unroll
    for (int i = 0; i < 4; i++) acc[i] = bo[lat0 + i];
    #pragma unroll 8
    for (int j = 0; j < 128; j++) {
        float xv = X[q * 132 + j];
        float4 wv = *(const float4*)&Wo[j * 32 + lat0];
        acc[0] += xv * wv.x; acc[1] += xv * wv.y;
        acc[2] += xv * wv.z; acc[3] += xv * wv.w;
    }
    *(float4*)(out + ((long)(b * LQ + qt * 32 + q)) * 32 + lat0) =
        make_float4(acc[0], acc[1], acc[2], acc[3]);
}

// ---------------- launch ------------------------------------------------------
extern "C" void kernel_launch(void* const* d_in, const int* in_sizes, int n_in,
                              void* d_out, int out_size)
{
    const float* query = (const float*)d_in[0];
    const float* key   = (const float*)d_in[1];
    const float* value = (const float*)d_in[2];
    const int*   mask  = (const int*)  d_in[3];
    const float* Wq    = (const float*)d_in[4];
    const float* bq    = (const float*)d_in[5];
    const float* Wk    = (const float*)d_in[6];
    const float* bk    = (const float*)d_in[7];
    const float* Wo    = (const float*)d_in[8];
    const float* bo    = (const float*)d_in[9];
    float* out = (float*)d_out;
    (void)in_sizes; (void)n_in; (void)out_size;

    const int smem = 4096 + 4 * 16384 + 1024;   // Q + 4 stages + align slack
    cudaFuncSetAttribute(attn_kernel, cudaFuncAttributeMaxDynamicSharedMemorySize, smem);

    prep_kernel<<<1600, 256>>>(query, key, value, mask, Wq, bq, Wk, bk);
    dim3 grid(LQ / 32, BB);
    attn_kernel<<<grid, 256, smem>>>(Wo, bo, out);
}

// round 7
// speedup vs baseline: 1.0579x; 1.0579x over previous
#include <cuda_runtime.h>
#include <cuda_fp16.h>
#include <cstdint>

#define BB 16
#define LQ 256
#define LK 4096

typedef unsigned long long ull;

// ---------------- device scratch (no allocation allowed) --------------------
__device__ __align__(16) __half g_qh [BB * LQ * 64];         // Q proj, f16, pre-scaled
__device__ __align__(16) __half g_kh [(long)BB * LK * 64];   // K proj, f16
__device__ __align__(16) __half g_wth[(long)BB * 64 * LK];   // Wt[b][d][kk] = [m*v | m]

// ---------------- helpers ----------------------------------------------------
__device__ __forceinline__ uint32_t smem_u32(const void* p) {
    uint32_t a;
    asm("{ .reg .u64 t; cvta.to.shared.u64 t, %1; cvt.u32.u64 %0, t; }" : "=r"(a) : "l"(p));
    return a;
}
__device__ __forceinline__ uint32_t f16x2_of(float lo, float hi) {
    uint32_t r; asm("cvt.rn.f16x2.f32 %0, %1, %2;" : "=r"(r) : "f"(hi), "f"(lo)); return r;
}
__device__ __forceinline__ uint32_t ex2x2(uint32_t a) {
    uint32_t r; asm("ex2.approx.f16x2 %0, %1;" : "=r"(r) : "r"(a)); return r;
}
__device__ __forceinline__ ull pack2(float lo, float hi) {
    ull r; asm("mov.b64 %0, {%1,%2};" : "=l"(r) : "f"(lo), "f"(hi)); return r;
}
__device__ __forceinline__ void unpack2(ull v, float& lo, float& hi) {
    asm("mov.b64 {%0,%1}, %2;" : "=f"(lo), "=f"(hi) : "l"(v));
}
__device__ __forceinline__ ull ffma2(ull a, ull b, ull c) {
    ull d; asm("fma.rn.f32x2 %0, %1, %2, %3;" : "=l"(d) : "l"(a), "l"(b), "l"(c));
    return d;
}
__device__ __forceinline__ void cp16(uint32_t dst, const void* src) {
    asm volatile("cp.async.ca.shared.global [%0], [%1], 16;" :: "r"(dst), "l"(src));
}
#define CP_COMMIT() asm volatile("cp.async.commit_group;" ::: "memory")
#define CP_WAIT(n)  asm volatile("cp.async.wait_group %0;" :: "n"(n) : "memory")

__device__ __forceinline__ void ldsm_x4(uint32_t* r, uint32_t a) {
    asm volatile("ldmatrix.sync.aligned.m8n8.x4.shared.b16 {%0,%1,%2,%3}, [%4];"
                 : "=r"(r[0]), "=r"(r[1]), "=r"(r[2]), "=r"(r[3]) : "r"(a));
}
__device__ __forceinline__ void mma_acc(float* d, const uint32_t* a, const uint32_t* b) {
    asm volatile("mma.sync.aligned.m16n8k16.row.col.f32.f16.f16.f32 "
        "{%0,%1,%2,%3}, {%4,%5,%6,%7}, {%8,%9}, {%0,%1,%2,%3};"
        : "+f"(d[0]), "+f"(d[1]), "+f"(d[2]), "+f"(d[3])
        : "r"(a[0]), "r"(a[1]), "r"(a[2]), "r"(a[3]), "r"(b[0]), "r"(b[1]));
}
__device__ __forceinline__ void mma_zro(float* d, const uint32_t* a, const uint32_t* b) {
    asm volatile("mma.sync.aligned.m16n8k16.row.col.f32.f16.f16.f32 "
        "{%0,%1,%2,%3}, {%4,%5,%6,%7}, {%8,%9}, {%10,%10,%10,%10};"
        : "=f"(d[0]), "=f"(d[1]), "=f"(d[2]), "=f"(d[3])
        : "r"(a[0]), "r"(a[1]), "r"(a[2]), "r"(a[3]), "r"(b[0]), "r"(b[1]), "f"(0.0f));
}

#define QSCALE 0.36067376022224085f   // 0.25 * log2(e)

// ---------------- fused prep: proj-q | proj-k | Wt build --------------------
// grid 1600: [0,64) proj q, [64,1088) proj k, [1088,1600) wt
__global__ void __launch_bounds__(256) prep_kernel(
    const float* __restrict__ qin, const float* __restrict__ kin,
    const float* __restrict__ v, const int* __restrict__ m,
    const float* __restrict__ Wq, const float* __restrict__ bq,
    const float* __restrict__ Wk, const float* __restrict__ bk)
{
    __shared__ __align__(16) float Wsh[64 * 64];
    __shared__ __align__(16) float Ish[64 * 68];
    const int bid = blockIdx.x, t = threadIdx.x;

    if (bid < 1088) {
        const int isq = (bid < 64);
        const float* in   = isq ? qin : kin;
        const float* W    = isq ? Wq : Wk;
        const float* bias = isq ? bq : bk;
        const float scale = isq ? QSCALE : 1.0f;
        __half* outp = isq ? g_qh : g_kh;
        const long row0 = (long)(isq ? bid : bid - 64) * 64;
        const float4* ing = (const float4*)(in + row0 * 64);
        #pragma unroll
        for (int i = t; i < 1024; i += 256) ((float4*)Wsh)[i] = ((const float4*)W)[i];
        #pragma unroll
        for (int i = t; i < 1024; i += 256) {
            int rr = i >> 4, c = i & 15;
            *(float4*)&Ish[rr * 68 + c * 4] = ing[i];
        }
        __syncthreads();

        const int e0 = (t & 15) * 4;
        const int rb = (t >> 4) * 4;
        float4 bv = *(const float4*)&bias[e0];
        ull a01 = pack2(bv.x, bv.y), a23 = pack2(bv.z, bv.w);
        ull acc[4][2];
        #pragma unroll
        for (int r = 0; r < 4; r++) { acc[r][0] = a01; acc[r][1] = a23; }
        #pragma unroll 8
        for (int j = 0; j < 64; j++) {
            ulonglong2 w = *(const ulonglong2*)&Wsh[j * 64 + e0];
            #pragma unroll
            for (int r = 0; r < 4; r++) {
                float iv = Ish[(rb + r) * 68 + j];
                ull dv = pack2(iv, iv);
                acc[r][0] = ffma2(dv, w.x, acc[r][0]);
                acc[r][1] = ffma2(dv, w.y, acc[r][1]);
            }
        }
        #pragma unroll
        for (int r = 0; r < 4; r++) {
            float v0, v1, v2, v3;
            unpack2(acc[r][0], v0, v1);
            unpack2(acc[r][1], v2, v3);
            uint2 u;
            u.x = f16x2_of(v0 * scale, v1 * scale);
            u.y = f16x2_of(v2 * scale, v3 * scale);
            *(uint2*)&outp[(row0 + rb + r) * 64 + e0] = u;
        }
    } else {
        // Wt build: g_wth[b][d][kk] = [m*v | m] (f16), via SMEM transpose
        __half* Wsm = (__half*)Wsh;           // [64][144] = 18KB, fits region
        const int id = bid - 1088;
        const int b = id >> 5, kt = id & 31;
        const long base = ((long)b * LK + kt * 128) * 32;
        for (int i = t; i < 4096; i += 256) {
            int kk = i >> 5, d = i & 31;
            float mv = (float)m[base + i];
            float vv = v[base + i];
            Wsm[d * 144 + kk]        = __float2half(mv * vv);
            Wsm[(d + 32) * 144 + kk] = __float2half(mv);
        }
        __syncthreads();
        for (int i = t; i < 1024; i += 256) {
            int row = i >> 4, c = i & 15;
            *(uint4*)(g_wth + ((long)b * 64 + row) * LK + kt * 128 + c * 8) =
                *(uint4*)&Wsm[row * 144 + c * 8];
        }
    }
}

// ---------------- main fused attention: 16 warps, 4 kk-streams/SMSP ---------
// grid (8 qt, 16 b), 512 threads = 16 warps: warp = (head h = w&3, kk-q s = w>>2).
// SMEM (dyn, 1KB-aligned): Q 4KB @0; stages c&3: K 8KB @4096+16384*(c&3), W @+8192.
// Epilogue: stageA @4096 (32KB), stageB @36864 (32KB), X reuses stageB.
__global__ void __launch_bounds__(512, 1) attn_kernel(
    const float* __restrict__ Wo, const float* __restrict__ bo,
    float* __restrict__ out)
{
    extern __shared__ __align__(16) char smraw[];
    const uint32_t base = smem_u32(smraw);
    const uint32_t sb = (base + 1023) & ~1023u;
    char* shb = smraw + (sb - base);

    const int t = threadIdx.x, l = t & 31, w = t >> 5;
    const int h = w & 3, s = w >> 2;
    const int qt = blockIdx.x, b = blockIdx.y;

    const char*   qg = (const char*)(g_qh + ((long)(b * LQ + qt * 32)) * 64);
    const __half* kg = g_kh  + (long)b * LK * 64;
    const __half* wg = g_wth + (long)b * 64 * LK;

    auto issue = [&](int c) {
        const uint32_t KB = sb + 4096 + (uint32_t)(c & 3) * 16384, WB = KB + 8192;
        const char* ks = (const char*)(kg + (long)c * 64 * 64);
        const int kk0 = c * 64;
        #pragma unroll
        for (int i = t; i < 1024; i += 512) {
            if (i < 512) {
                uint32_t off = i * 16, sw = off ^ ((off >> 3) & 0x70);
                cp16(KB + sw, ks + off);
            } else {
                int j = i - 512;
                uint32_t off = j * 16, sw = off ^ ((off >> 3) & 0x70);
                cp16(WB + sw, (const char*)(wg + (long)(j >> 3) * LK + kk0) + (j & 7) * 16);
            }
        }
    };

    // group 0: Q + chunk 0; groups 1,2: chunks 1,2
    if (t < 256) {
        uint32_t off = t * 16, sw = off ^ ((off >> 3) & 0x70);
        cp16(sb + sw, qg + off);
    }
    issue(0); CP_COMMIT();
    issue(1); CP_COMMIT();
    issue(2); CP_COMMIT();

    // per-lane ldmatrix x4 address pieces
    const int li = l & 7, m4 = l >> 3;           // m4: matrix index 0..3
    // K (GEMM1 B, n=kk, k=e): row = s*16 + (m4>>1)*8 + li, col = h*32 + (m4&1)*16
    const uint32_t kBase = (uint32_t)(s * 16 + (m4 >> 1) * 8 + li) * 128
                         + (((uint32_t)(h * 32 + (m4 & 1) * 16)) ^ ((uint32_t)li << 4));
    // W (GEMM2 B, n=d, k=kk): row = (m4>>1)*8 + li, col = s*32 + (m4&1)*16 (+p*2048)
    const uint32_t wBase = (uint32_t)((m4 >> 1) * 8 + li) * 128
                         + (((uint32_t)(s * 32 + (m4 & 1) * 16)) ^ ((uint32_t)li << 4));

    CP_WAIT(2);
    __syncthreads();

    // Q A-frags (constant over chunks)
    uint32_t aq[2][4];
    {
        const int quad = l >> 3;
        const uint32_t arow = (uint32_t)((quad & 1) * 8 + li) * 128;
        const uint32_t acol = ((uint32_t)(h * 32 + (quad >> 1) * 16)) ^ ((uint32_t)li << 4);
        ldsm_x4(aq[0], sb + 0    + arow + acol);
        ldsm_x4(aq[1], sb + 2048 + arow + acol);
    }

    float O[2][8][4];
    #pragma unroll
    for (int mt = 0; mt < 2; mt++)
        #pragma unroll
        for (int nt = 0; nt < 8; nt++)
            #pragma unroll
            for (int i = 0; i < 4; i++) O[mt][nt][i] = 0.0f;

    for (int c = 0; c < 64; c++) {
        if (c) { CP_WAIT(2); __syncthreads(); }
        if (c + 3 < 64) issue(c + 3);
        CP_COMMIT();

        const uint32_t KBp = sb + 4096 + (uint32_t)(c & 3) * 16384, WBp = KBp + 8192;

        // GEMM1 + exp: warp covers kk [s*16, s*16+16) = 2 n-tiles in one ldsm_x4
        uint32_t E[2][4];
        {
            uint32_t kf[4];
            ldsm_x4(kf, KBp + kBase);
            #pragma unroll
            for (int mt = 0; mt < 2; mt++) {
                float s0[4], s1[4];
                mma_zro(s0, aq[mt], kf);        // kk tile 0 (b = kf0,kf1)
                mma_zro(s1, aq[mt], kf + 2);    // kk tile 1 (b = kf2,kf3)
                E[mt][0] = ex2x2(f16x2_of(s0[0], s0[1]));
                E[mt][1] = ex2x2(f16x2_of(s0[2], s0[3]));
                E[mt][2] = ex2x2(f16x2_of(s1[0], s1[1]));
                E[mt][3] = ex2x2(f16x2_of(s1[2], s1[3]));
            }
        }

        // GEMM2: O += E . Wt^T over this warp's 16 kk; 8 n-tiles in 4 ldsm_x4
        #pragma unroll
        for (int p = 0; p < 4; p++) {
            uint32_t wf[4];
            ldsm_x4(wf, WBp + wBase + (uint32_t)p * 2048);
            mma_acc(O[0][2 * p],     E[0], wf);
            mma_acc(O[0][2 * p + 1], E[0], wf + 2);
            mma_acc(O[1][2 * p],     E[1], wf);
            mma_acc(O[1][2 * p + 1], E[1], wf + 2);
        }
    }

    // ---- epilogue: tree-reduce s=0..3, X = num/den, out = X @ Wo + bo -------
    float* stA = (float*)(shb + 4096);
    float* stB = (float*)(shb + 36864);
    #define ST_IDX(q, col) ((q) * 64 + ((col) ^ (((q) & 3) << 3)))

    if (s == 1 || s == 3) {
        float* dst = (s == 1) ? stA : stB;
        #pragma unroll
        for (int mt = 0; mt < 2; mt++)
            #pragma unroll
            for (int nt = 0; nt < 8; nt++)
                #pragma unroll
                for (int i = 0; i < 4; i++) {
                    int q = mt * 16 + (l >> 2) + ((i >> 1) & 1) * 8;
                    int col = nt * 8 + 2 * (l & 3) + (i & 1);
                    dst[h * 2048 + ST_IDX(q, col)] = O[mt][nt][i];
                }
    }
    __syncthreads();
    if (s == 0 || s == 2) {
        float* src = (s == 0) ? stA : stB;
        #pragma unroll
        for (int mt = 0; mt < 2; mt++)
            #pragma unroll
            for (int nt = 0; nt < 8; nt++)
                #pragma unroll
                for (int i = 0; i < 4; i++) {
                    int q = mt * 16 + (l >> 2) + ((i >> 1) & 1) * 8;
                    int col = nt * 8 + 2 * (l & 3) + (i & 1);
                    O[mt][nt][i] += src[h * 2048 + ST_IDX(q, col)];
                }
    }
    __syncthreads();
    if (s == 2) {
        #pragma unroll
        for (int mt = 0; mt < 2; mt++)
            #pragma unroll
            for (int nt = 0; nt < 8; nt++)
                #pragma unroll
                for (int i = 0; i < 4; i++) {
                    int q = mt * 16 + (l >> 2) + ((i >> 1) & 1) * 8;
                    int col = nt * 8 + 2 * (l & 3) + (i & 1);
                    stA[h * 2048 + ST_IDX(q, col)] = O[mt][nt][i];
                }
    }
    __syncthreads();
    float* X = (float*)(shb + 36864);       // [32][132]
    if (s == 0) {
        #pragma unroll
        for (int mt = 0; mt < 2; mt++)
            #pragma unroll
            for (int nt = 0; nt < 8; nt++)
                #pragma unroll
                for (int i = 0; i < 4; i++) {
                    int q = mt * 16 + (l >> 2) + ((i >> 1) & 1) * 8;
                    int col = nt * 8 + 2 * (l & 3) + (i & 1);
                    O[mt][nt][i] += stA[h * 2048 + ST_IDX(q, col)];
                }
        #pragma unroll
        for (int mt = 0; mt < 2; mt++)
            #pragma unroll
            for (int nt = 0; nt < 4; nt++)
                #pragma unroll
                for (int i = 0; i < 4; i++) {
                    float x = __fdividef(O[mt][nt][i], O[mt][nt + 4][i]);
                    int q = mt * 16 + (l >> 2) + ((i >> 1) & 1) * 8;
                    int col = h * 32 + nt * 8 + 2 * (l & 3) + (i & 1);
                    X[q * 132 + col] = x;
                }
    }
    __syncthreads();

    const int q = t >> 4, latp = (t & 15) * 2;
    float a0 = bo[latp], a1 = bo[latp + 1];
    #pragma unroll 8
    for (int j = 0; j < 128; j++) {
        float xv = X[q * 132 + j];
        float2 wv = *(const float2*)&Wo[j * 32 + latp];
        a0 += xv * wv.x; a1 += xv * wv.y;
    }
    *(float2*)(out + ((long)(b * LQ + qt * 32 + q)) * 32 + latp) =
        make_float2(a0, a1);
}

// ---------------- launch ------------------------------------------------------
extern "C" void kernel_launch(void* const* d_in, const int* in_sizes, int n_in,
                              void* d_out, int out_size)
{
    const float* query = (const float*)d_in[0];
    const float* key   = (const float*)d_in[1];
    const float* value = (const float*)d_in[2];
    const int*   mask  = (const int*)  d_in[3];
    const float* Wq    = (const float*)d_in[4];
    const float* bq    = (const float*)d_in[5];
    const float* Wk    = (const float*)d_in[6];
    const float* bk    = (const float*)d_in[7];
    const float* Wo    = (const float*)d_in[8];
    const float* bo    = (const float*)d_in[9];
    float* out = (float*)d_out;
    (void)in_sizes; (void)n_in; (void)out_size;

    const int smem = 4096 + 4 * 16384 + 1024;   // Q + 4 stages + align slack
    cudaFuncSetAttribute(attn_kernel, cudaFuncAttributeMaxDynamicSharedMemorySize, smem);

    prep_kernel<<<1600, 256>>>(query, key, value, mask, Wq, bq, Wk, bk);
    dim3 grid(LQ / 32, BB);
    attn_kernel<<<grid, 512, smem>>>(Wo, bo, out);
}

// round 8
// speedup vs baseline: 1.0626x; 1.0044x over previous
#include <cuda_runtime.h>
#include <cuda_fp16.h>
#include <cstdint>

#define BB 16
#define LQ 256
#define LK 4096

typedef unsigned long long ull;

// ---------------- device scratch (no allocation allowed) --------------------
__device__ __align__(16) __half g_qh [BB * LQ * 64];         // Q proj, f16, pre-scaled
__device__ __align__(16) __half g_kh [(long)BB * LK * 64];   // K proj, f16
__device__ __align__(16) __half g_wth[(long)BB * 64 * LK];   // Wt[b][d][kk] = [m*v | m]

// ---------------- helpers ----------------------------------------------------
__device__ __forceinline__ uint32_t smem_u32(const void* p) {
    uint32_t a;
    asm("{ .reg .u64 t; cvta.to.shared.u64 t, %1; cvt.u32.u64 %0, t; }" : "=r"(a) : "l"(p));
    return a;
}
__device__ __forceinline__ uint32_t f16x2_of(float lo, float hi) {
    uint32_t r; asm("cvt.rn.f16x2.f32 %0, %1, %2;" : "=r"(r) : "f"(hi), "f"(lo)); return r;
}
__device__ __forceinline__ uint32_t ex2x2(uint32_t a) {
    uint32_t r; asm("ex2.approx.f16x2 %0, %1;" : "=r"(r) : "r"(a)); return r;
}
__device__ __forceinline__ ull pack2(float lo, float hi) {
    ull r; asm("mov.b64 %0, {%1,%2};" : "=l"(r) : "f"(lo), "f"(hi)); return r;
}
__device__ __forceinline__ void unpack2(ull v, float& lo, float& hi) {
    asm("mov.b64 {%0,%1}, %2;" : "=f"(lo), "=f"(hi) : "l"(v));
}
__device__ __forceinline__ ull ffma2(ull a, ull b, ull c) {
    ull d; asm("fma.rn.f32x2 %0, %1, %2, %3;" : "=l"(d) : "l"(a), "l"(b), "l"(c));
    return d;
}
__device__ __forceinline__ void cp16(uint32_t dst, const void* src) {
    asm volatile("cp.async.ca.shared.global [%0], [%1], 16;" :: "r"(dst), "l"(src));
}
#define CP_COMMIT() asm volatile("cp.async.commit_group;" ::: "memory")
#define CP_WAIT(n)  asm volatile("cp.async.wait_group %0;" :: "n"(n) : "memory")

__device__ __forceinline__ void ldsm_x4(uint32_t* r, uint32_t a) {
    asm volatile("ldmatrix.sync.aligned.m8n8.x4.shared.b16 {%0,%1,%2,%3}, [%4];"
                 : "=r"(r[0]), "=r"(r[1]), "=r"(r[2]), "=r"(r[3]) : "r"(a));
}
__device__ __forceinline__ void mma_acc(float* d, const uint32_t* a, const uint32_t* b) {
    asm volatile("mma.sync.aligned.m16n8k16.row.col.f32.f16.f16.f32 "
        "{%0,%1,%2,%3}, {%4,%5,%6,%7}, {%8,%9}, {%0,%1,%2,%3};"
        : "+f"(d[0]), "+f"(d[1]), "+f"(d[2]), "+f"(d[3])
        : "r"(a[0]), "r"(a[1]), "r"(a[2]), "r"(a[3]), "r"(b[0]), "r"(b[1]));
}
__device__ __forceinline__ void mma_zro(float* d, const uint32_t* a, const uint32_t* b) {
    asm volatile("mma.sync.aligned.m16n8k16.row.col.f32.f16.f16.f32 "
        "{%0,%1,%2,%3}, {%4,%5,%6,%7}, {%8,%9}, {%10,%10,%10,%10};"
        : "=f"(d[0]), "=f"(d[1]), "=f"(d[2]), "=f"(d[3])
        : "r"(a[0]), "r"(a[1]), "r"(a[2]), "r"(a[3]), "r"(b[0]), "r"(b[1]), "f"(0.0f));
}

#define QSCALE 0.36067376022224085f   // 0.25 * log2(e)

// ---------------- fused prep: proj-q | proj-k | Wt build --------------------
// grid 1600: [0,64) proj q, [64,1088) proj k, [1088,1600) wt
__global__ void __launch_bounds__(256) prep_kernel(
    const float* __restrict__ qin, const float* __restrict__ kin,
    const float* __restrict__ v, const int* __restrict__ m,
    const float* __restrict__ Wq, const float* __restrict__ bq,
    const float* __restrict__ Wk, const float* __restrict__ bk)
{
    __shared__ __align__(16) float Wsh[64 * 64];
    __shared__ __align__(16) float Ish[64 * 68];
    const int bid = blockIdx.x, t = threadIdx.x;

    if (bid < 1088) {
        const int isq = (bid < 64);
        const float* in   = isq ? qin : kin;
        const float* W    = isq ? Wq : Wk;
        const float* bias = isq ? bq : bk;
        const float scale = isq ? QSCALE : 1.0f;
        __half* outp = isq ? g_qh : g_kh;
        const long row0 = (long)(isq ? bid : bid - 64) * 64;
        const float4* ing = (const float4*)(in + row0 * 64);
        #pragma unroll
        for (int i = t; i < 1024; i += 256) ((float4*)Wsh)[i] = ((const float4*)W)[i];
        #pragma unroll
        for (int i = t; i < 1024; i += 256) {
            int rr = i >> 4, c = i & 15;
            *(float4*)&Ish[rr * 68 + c * 4] = ing[i];
        }
        __syncthreads();

        const int e0 = (t & 15) * 4;
        const int rb = (t >> 4) * 4;
        float4 bv = *(const float4*)&bias[e0];
        ull a01 = pack2(bv.x, bv.y), a23 = pack2(bv.z, bv.w);
        ull acc[4][2];
        #pragma unroll
        for (int r = 0; r < 4; r++) { acc[r][0] = a01; acc[r][1] = a23; }
        #pragma unroll 8
        for (int j = 0; j < 64; j++) {
            ulonglong2 w = *(const ulonglong2*)&Wsh[j * 64 + e0];
            #pragma unroll
            for (int r = 0; r < 4; r++) {
                float iv = Ish[(rb + r) * 68 + j];
                ull dv = pack2(iv, iv);
                acc[r][0] = ffma2(dv, w.x, acc[r][0]);
                acc[r][1] = ffma2(dv, w.y, acc[r][1]);
            }
        }
        #pragma unroll
        for (int r = 0; r < 4; r++) {
            float v0, v1, v2, v3;
            unpack2(acc[r][0], v0, v1);
            unpack2(acc[r][1], v2, v3);
            uint2 u;
            u.x = f16x2_of(v0 * scale, v1 * scale);
            u.y = f16x2_of(v2 * scale, v3 * scale);
            *(uint2*)&outp[(row0 + rb + r) * 64 + e0] = u;
        }
    } else {
        // Wt build: g_wth[b][d][kk] = [m*v | m] (f16), via SMEM transpose
        __half* Wsm = (__half*)Wsh;           // [64][144] = 18KB, fits region
        const int id = bid - 1088;
        const int b = id >> 5, kt = id & 31;
        const long base = ((long)b * LK + kt * 128) * 32;
        for (int i = t; i < 4096; i += 256) {
            int kk = i >> 5, d = i & 31;
            float mv = (float)m[base + i];
            float vv = v[base + i];
            Wsm[d * 144 + kk]        = __float2half(mv * vv);
            Wsm[(d + 32) * 144 + kk] = __float2half(mv);
        }
        __syncthreads();
        for (int i = t; i < 1024; i += 256) {
            int row = i >> 4, c = i & 15;
            *(uint4*)(g_wth + ((long)b * 64 + row) * LK + kt * 128 + c * 8) =
                *(uint4*)&Wsm[row * 144 + c * 8];
        }
    }
}

// ---------------- main fused attention: cross-chunk software pipeline -------
// grid (8 qt, 16 b), 512 threads = 16 warps: warp = (head h = w&3, kk-q s = w>>2).
// Per iter c: GEMM1(c) + GEMM2(c-1) back-to-back (20 mma), THEN exp(c) -> E
// carried to next iter. Prefetch distance 2; stages in use: c-1 (W), c, c+1, c+2.
// SMEM (dyn, 1KB-aligned): Q 4KB @0; stage c&3: K 8KB @4096+16384*(c&3), W @+8192.
// Epilogue: stageA @4096, stageB @36864 (after barrier; aliases stages).
__global__ void __launch_bounds__(512, 1) attn_kernel(
    const float* __restrict__ Wo, const float* __restrict__ bo,
    float* __restrict__ out)
{
    extern __shared__ __align__(16) char smraw[];
    const uint32_t base = smem_u32(smraw);
    const uint32_t sb = (base + 1023) & ~1023u;
    char* shb = smraw + (sb - base);

    const int t = threadIdx.x, l = t & 31, w = t >> 5;
    const int h = w & 3, s = w >> 2;
    const int qt = blockIdx.x, b = blockIdx.y;

    const char*   qg = (const char*)(g_qh + ((long)(b * LQ + qt * 32)) * 64);
    const __half* kg = g_kh  + (long)b * LK * 64;
    const __half* wg = g_wth + (long)b * 64 * LK;

    auto issue = [&](int c) {
        const uint32_t KB = sb + 4096 + (uint32_t)(c & 3) * 16384, WB = KB + 8192;
        const char* ks = (const char*)(kg + (long)c * 64 * 64);
        const int kk0 = c * 64;
        #pragma unroll
        for (int i = t; i < 1024; i += 512) {
            if (i < 512) {
                uint32_t off = i * 16, sw = off ^ ((off >> 3) & 0x70);
                cp16(KB + sw, ks + off);
            } else {
                int j = i - 512;
                uint32_t off = j * 16, sw = off ^ ((off >> 3) & 0x70);
                cp16(WB + sw, (const char*)(wg + (long)(j >> 3) * LK + kk0) + (j & 7) * 16);
            }
        }
    };

    // group 0: Q + chunk 0; group 1: chunk 1  (prefetch distance 2)
    if (t < 256) {
        uint32_t off = t * 16, sw = off ^ ((off >> 3) & 0x70);
        cp16(sb + sw, qg + off);
    }
    issue(0); CP_COMMIT();
    issue(1); CP_COMMIT();

    // per-lane ldmatrix x4 address pieces
    const int li = l & 7, m4 = l >> 3;
    const uint32_t kBase = (uint32_t)(s * 16 + (m4 >> 1) * 8 + li) * 128
                         + (((uint32_t)(h * 32 + (m4 & 1) * 16)) ^ ((uint32_t)li << 4));
    const uint32_t wBase = (uint32_t)((m4 >> 1) * 8 + li) * 128
                         + (((uint32_t)(s * 32 + (m4 & 1) * 16)) ^ ((uint32_t)li << 4));

    CP_WAIT(1);
    __syncthreads();   // Q + stage 0 ready

    // Q A-frags (constant over chunks)
    uint32_t aq[2][4];
    {
        const int quad = l >> 3;
        const uint32_t arow = (uint32_t)((quad & 1) * 8 + li) * 128;
        const uint32_t acol = ((uint32_t)(h * 32 + (quad >> 1) * 16)) ^ ((uint32_t)li << 4);
        ldsm_x4(aq[0], sb + 0    + arow + acol);
        ldsm_x4(aq[1], sb + 2048 + arow + acol);
    }

    float O[2][8][4];
    #pragma unroll
    for (int mt = 0; mt < 2; mt++)
        #pragma unroll
        for (int nt = 0; nt < 8; nt++)
            #pragma unroll
            for (int i = 0; i < 4; i++) O[mt][nt][i] = 0.0f;

    uint32_t E[2][4];   // E of chunk c-1, carried across iterations

    for (int c = 0; c < 64; c++) {
        if (c) { CP_WAIT(1); __syncthreads(); }   // stage c ready; stage (c-2)&3 free
        if (c + 2 < 64) issue(c + 2);
        CP_COMMIT();                               // uniform group counting

        const uint32_t KBp = sb + 4096 + (uint32_t)(c & 3) * 16384;

        // GEMM1(c): 4 mma into S
        uint32_t kf[4];
        ldsm_x4(kf, KBp + kBase);
        float S[2][2][4];
        mma_zro(S[0][0], aq[0], kf);
        mma_zro(S[0][1], aq[0], kf + 2);
        mma_zro(S[1][0], aq[1], kf);
        mma_zro(S[1][1], aq[1], kf + 2);

        // GEMM2(c-1): 16 mma, immediately after (tensor pipe stays fed)
        if (c) {
            const uint32_t WBprev = sb + 4096 + (uint32_t)((c - 1) & 3) * 16384 + 8192;
            #pragma unroll
            for (int p = 0; p < 4; p++) {
                uint32_t wf[4];
                ldsm_x4(wf, WBprev + wBase + (uint32_t)p * 2048);
                mma_acc(O[0][2 * p],     E[0], wf);
                mma_acc(O[0][2 * p + 1], E[0], wf + 2);
                mma_acc(O[1][2 * p],     E[1], wf);
                mma_acc(O[1][2 * p + 1], E[1], wf + 2);
            }
        }

        // exp(c): overlaps other warps' mma; result feeds next iter's GEMM2
        #pragma unroll
        for (int mt = 0; mt < 2; mt++) {
            E[mt][0] = ex2x2(f16x2_of(S[mt][0][0], S[mt][0][1]));
            E[mt][1] = ex2x2(f16x2_of(S[mt][0][2], S[mt][0][3]));
            E[mt][2] = ex2x2(f16x2_of(S[mt][1][0], S[mt][1][1]));
            E[mt][3] = ex2x2(f16x2_of(S[mt][1][2], S[mt][1][3]));
        }
    }

    // drain: GEMM2(63) from stage 3
    {
        const uint32_t WBlast = sb + 4096 + (uint32_t)(63 & 3) * 16384 + 8192;
        #pragma unroll
        for (int p = 0; p < 4; p++) {
            uint32_t wf[4];
            ldsm_x4(wf, WBlast + wBase + (uint32_t)p * 2048);
            mma_acc(O[0][2 * p],     E[0], wf);
            mma_acc(O[0][2 * p + 1], E[0], wf + 2);
            mma_acc(O[1][2 * p],     E[1], wf);
            mma_acc(O[1][2 * p + 1], E[1], wf + 2);
        }
    }
    __syncthreads();   // all warps done reading stages before epilogue aliases them

    // ---- epilogue: tree-reduce s=0..3, X = num/den, out = X @ Wo + bo -------
    float* stA = (float*)(shb + 4096);
    float* stB = (float*)(shb + 36864);
    #define ST_IDX(q, col) ((q) * 64 + ((col) ^ (((q) & 3) << 3)))

    if (s == 1 || s == 3) {
        float* dst = (s == 1) ? stA : stB;
        #pragma unroll
        for (int mt = 0; mt < 2; mt++)
            #pragma unroll
            for (int nt = 0; nt < 8; nt++)
                #pragma unroll
                for (int i = 0; i < 4; i++) {
                    int q = mt * 16 + (l >> 2) + ((i >> 1) & 1) * 8;
                    int col = nt * 8 + 2 * (l & 3) + (i & 1);
                    dst[h * 2048 + ST_IDX(q, col)] = O[mt][nt][i];
                }
    }
    __syncthreads();
    if (s == 0 || s == 2) {
        float* src = (s == 0) ? stA : stB;
        #pragma unroll
        for (int mt = 0; mt < 2; mt++)
            #pragma unroll
            for (int nt = 0; nt < 8; nt++)
                #pragma unroll
                for (int i = 0; i < 4; i++) {
                    int q = mt * 16 + (l >> 2) + ((i >> 1) & 1) * 8;
                    int col = nt * 8 + 2 * (l & 3) + (i & 1);
                    O[mt][nt][i] += src[h * 2048 + ST_IDX(q, col)];
                }
    }
    __syncthreads();
    if (s == 2) {
        #pragma unroll
        for (int mt = 0; mt < 2; mt++)
            #pragma unroll
            for (int nt = 0; nt < 8; nt++)
                #pragma unroll
                for (int i = 0; i < 4; i++) {
                    int q = mt * 16 + (l >> 2) + ((i >> 1) & 1) * 8;
                    int col = nt * 8 + 2 * (l & 3) + (i & 1);
                    stA[h * 2048 + ST_IDX(q, col)] = O[mt][nt][i];
                }
    }
    __syncthreads();
    float* X = (float*)(shb + 36864);       // [32][132]
    if (s == 0) {
        #pragma unroll
        for (int mt = 0; mt < 2; mt++)
            #pragma unroll
            for (int nt = 0; nt < 8; nt++)
                #pragma unroll
                for (int i = 0; i < 4; i++) {
                    int q = mt * 16 + (l >> 2) + ((i >> 1) & 1) * 8;
                    int col = nt * 8 + 2 * (l & 3) + (i & 1);
                    O[mt][nt][i] += stA[h * 2048 + ST_IDX(q, col)];
                }
        #pragma unroll
        for (int mt = 0; mt < 2; mt++)
            #pragma unroll
            for (int nt = 0; nt < 4; nt++)
                #pragma unroll
                for (int i = 0; i < 4; i++) {
                    float x = __fdividef(O[mt][nt][i], O[mt][nt + 4][i]);
                    int q = mt * 16 + (l >> 2) + ((i >> 1) & 1) * 8;
                    int col = h * 32 + nt * 8 + 2 * (l & 3) + (i & 1);
                    X[q * 132 + col] = x;
                }
    }
    __syncthreads();

    const int q = t >> 4, latp = (t & 15) * 2;
    float a0 = bo[latp], a1 = bo[latp + 1];
    #pragma unroll 8
    for (int j = 0; j < 128; j++) {
        float xv = X[q * 132 + j];
        float2 wv = *(const float2*)&Wo[j * 32 + latp];
        a0 += xv * wv.x; a1 += xv * wv.y;
    }
    *(float2*)(out + ((long)(b * LQ + qt * 32 + q)) * 32 + latp) =
        make_float2(a0, a1);
}

// ---------------- launch ------------------------------------------------------
extern "C" void kernel_launch(void* const* d_in, const int* in_sizes, int n_in,
                              void* d_out, int out_size)
{
    const float* query = (const float*)d_in[0];
    const float* key   = (const float*)d_in[1];
    const float* value = (const float*)d_in[2];
    const int*   mask  = (const int*)  d_in[3];
    const float* Wq    = (const float*)d_in[4];
    const float* bq    = (const float*)d_in[5];
    const float* Wk    = (const float*)d_in[6];
    const float* bk    = (const float*)d_in[7];
    const float* Wo    = (const float*)d_in[8];
    const float* bo    = (const float*)d_in[9];
    float* out = (float*)d_out;
    (void)in_sizes; (void)n_in; (void)out_size;

    const int smem = 4096 + 4 * 16384 + 1024;   // Q + 4 stages + align slack
    cudaFuncSetAttribute(attn_kernel, cudaFuncAttributeMaxDynamicSharedMemorySize, smem);

    prep_kernel<<<1600, 256>>>(query, key, value, mask, Wq, bq, Wk, bk);
    dim3 grid(LQ / 32, BB);
    attn_kernel<<<grid, 512, smem>>>(Wo, bo, out);
}